// round 16
// baseline (speedup 1.0000x reference)
#include <cuda_runtime.h>
#include <cstdint>

#define S_LEN 101
#define BATCH 2048
#define HID 200
#define DIN 120
#define DOUT 12
#define M_TOTAL (S_LEN * BATCH)   // 206848

// Scratch (no allocations allowed -> __device__ globals)
__device__ float g_cur[(size_t)M_TOTAL * HID];        // ~165 MB  cur[b][t][n]

typedef unsigned long long ull;

// ---------- packed f32x2 helpers ----------
__device__ __forceinline__ ull pack2(float lo, float hi) {
    ull r; asm("mov.b64 %0, {%1,%2};" : "=l"(r) : "f"(lo), "f"(hi)); return r;
}
__device__ __forceinline__ void unpack2(ull v, float& lo, float& hi) {
    asm("mov.b64 {%0,%1}, %2;" : "=f"(lo), "=f"(hi) : "l"(v));
}
__device__ __forceinline__ ull add2(ull a, ull b) {
    ull d; asm("add.rn.f32x2 %0, %1, %2;" : "=l"(d) : "l"(a), "l"(b)); return d;
}

// ---------- bf16 / mma helpers ----------
__device__ __forceinline__ unsigned bf16x2of(float lo, float hi) {
    unsigned r; asm("cvt.rn.bf16x2.f32 %0, %1, %2;" : "=r"(r) : "f"(hi), "f"(lo));
    return r;   // lo -> bits[0:16), hi -> bits[16:32)
}
__device__ __forceinline__ void bf16_hilo(float x0, float x1, unsigned& h, unsigned& l) {
    h = bf16x2of(x0, x1);
    float h0 = __uint_as_float(h << 16);
    float h1 = __uint_as_float(h & 0xffff0000u);
    l = bf16x2of(x0 - h0, x1 - h1);
}
__device__ __forceinline__ void mma_bf16(float* c,
                                         unsigned a0, unsigned a1, unsigned a2, unsigned a3,
                                         unsigned b0, unsigned b1) {
    asm volatile(
        "mma.sync.aligned.m16n8k16.row.col.f32.bf16.bf16.f32 "
        "{%0,%1,%2,%3}, {%4,%5,%6,%7}, {%8,%9}, {%0,%1,%2,%3};"
        : "+f"(c[0]), "+f"(c[1]), "+f"(c[2]), "+f"(c[3])
        : "r"(a0), "r"(a1), "r"(a2), "r"(a3), "r"(b0), "r"(b1));
}

// ================= Kernel 1: CUR1 = X @ W1 + b1, stage-free (R15, proven) ====
#define GM_THREADS 512
#define NFMAX 13
#define BF_BYTES (8 * NFMAX * 32 * 16)                 // 53248
#define MTILES2 (M_TOTAL / 256)                        // 808 exact

__global__ __launch_bounds__(GM_THREADS, 1)
void gemm1_mma_kernel(const float* __restrict__ x,
                      const float* __restrict__ W1,
                      const float* __restrict__ b1) {
    extern __shared__ char sm[];
    uint4* Bf = (uint4*)sm;                            // [8][13][32]

    const int tid   = threadIdx.x;
    const int warp  = tid >> 5;                        // 0..15
    const int lane  = tid & 31;
    const int group = lane >> 2;                       // 0..7
    const int tg    = lane & 3;                        // 0..3
    const int half  = blockIdx.x & 1;
    const int colbase = half ? 104 : 0;
    const int nfc     = half ? 12 : 13;

    for (int idx = tid; idx < 8 * nfc * 32; idx += GM_THREADS) {
        int ks  = idx / (nfc * 32);
        int rem = idx - ks * nfc * 32;
        int nf  = rem >> 5;
        int t   = rem & 31;
        int g = t >> 2, q = t & 3;
        int n  = colbase + nf * 8 + g;
        int k0 = ks * 16 + 2 * q;
        int k1 = k0 + 8;
        float w00 = W1[k0 * HID + n];
        float w01 = W1[(k0 + 1) * HID + n];
        float w10 = (k1     < DIN) ? W1[k1 * HID + n]       : 0.f;
        float w11 = (k1 + 1 < DIN) ? W1[(k1 + 1) * HID + n] : 0.f;
        unsigned b0h, b0l, b1h, b1l;
        bf16_hilo(w00, w01, b0h, b0l);
        bf16_hilo(w10, w11, b1h, b1l);
        Bf[(ks * NFMAX + nf) * 32 + t] = make_uint4(b0h, b1h, b0l, b1l);
    }

    float2 bias[NFMAX];
    #pragma unroll
    for (int nf = 0; nf < NFMAX; nf++) {
        if (nf < nfc) {
            int c = colbase + nf * 8 + 2 * tg;
            bias[nf] = make_float2(b1[c], b1[c + 1]);
        } else bias[nf] = make_float2(0.f, 0.f);
    }
    __syncthreads();                                   // Bf visible; no more bars

    for (int mt = blockIdx.x >> 1; mt < MTILES2; mt += 74) {
        const int rowg = mt * 256 + warp * 16 + group;
        const int rowh = rowg + 8;
        int bg = rowg / S_LEN, tg0 = rowg - bg * S_LEN;
        int bh = rowh / S_LEN, th0 = rowh - bh * S_LEN;
        const float* r0p = x + (size_t)(bg * 303 + tg0) * 40;
        const float* r1p = x + (size_t)(bh * 303 + th0) * 40;

        float acc[NFMAX][4];
        #pragma unroll
        for (int nf = 0; nf < NFMAX; nf++) {
            acc[nf][0] = bias[nf].x; acc[nf][1] = bias[nf].y;
            acc[nf][2] = bias[nf].x; acc[nf][3] = bias[nf].y;
        }

        #pragma unroll
        for (int ks = 0; ks < 8; ks++) {
            const int ka = ks * 16 + 2 * tg;
            const int ca = ka / 40, ma = ka - ca * 40;
            float2 p0 = *(const float2*)(r0p + ca * 4040 + ma);
            float2 p1 = *(const float2*)(r1p + ca * 4040 + ma);
            float2 p2, p3;
            if (ks < 7) {
                const int kb = ka + 8;
                const int cb = kb / 40, mb = kb - cb * 40;
                p2 = *(const float2*)(r0p + cb * 4040 + mb);
                p3 = *(const float2*)(r1p + cb * 4040 + mb);
            } else {
                p2 = make_float2(0.f, 0.f);
                p3 = make_float2(0.f, 0.f);
            }
            unsigned ah0, al0, ah1, al1, ah2, al2, ah3, al3;
            bf16_hilo(p0.x, p0.y, ah0, al0);
            bf16_hilo(p1.x, p1.y, ah1, al1);
            bf16_hilo(p2.x, p2.y, ah2, al2);
            bf16_hilo(p3.x, p3.y, ah3, al3);

            const uint4* bp = Bf + ks * NFMAX * 32 + lane;
            #pragma unroll
            for (int nf = 0; nf < NFMAX; nf++) {
                if (nf < nfc) {
                    uint4 b = bp[nf * 32];                        // LDS.128
                    mma_bf16(acc[nf], ah0, ah1, ah2, ah3, b.x, b.y);
                    mma_bf16(acc[nf], ah0, ah1, ah2, ah3, b.z, b.w);
                    mma_bf16(acc[nf], al0, al1, al2, al3, b.x, b.y);
                }
            }
        }

        float* op = g_cur + (size_t)rowg * HID + colbase;
        #pragma unroll
        for (int nf = 0; nf < NFMAX; nf++) {
            if (nf < nfc) {
                *(float2*)(op + nf * 8 + 2 * tg) =
                    make_float2(acc[nf][0], acc[nf][1]);
                *(float2*)(op + 8 * HID + nf * 8 + 2 * tg) =
                    make_float2(acc[nf][2], acc[nf][3]);
            }
        }
    }
}

// ========== Kernel 2: FUSED LIF with in-warp dual scan =======================
// 14 warps/CTA, warp = batch element. Lane (lane<25) owns neurons 8L..8L+7.
// scan2(t) and scan3(t-1) are independent -> interleaved in ONE warp-uniform
// loop (two independent LDS+add chains per iteration; empty slot -> zero row
// 200). mk2 carried across t in registers. No barriers, no handoff.
#define L_GROUPS 14
#define L_THREADS (L_GROUPS * 32)               // 448
#define LROWS 201
#define LSTRIDE (LROWS * 100)                   // u32 words per layer (20100)
#define LF_SMEM (2 * LSTRIDE * 4)               // 160800 B

__device__ __forceinline__ float bfLO(unsigned u) { return __uint_as_float(u << 16); }
__device__ __forceinline__ float bfHI(unsigned u) { return __uint_as_float(u & 0xffff0000u); }

__global__ __launch_bounds__(L_THREADS, 1)
void lif23_kernel(const float* __restrict__ W2, const float* __restrict__ b2,
                  const float* __restrict__ W3, const float* __restrict__ b3,
                  const float* __restrict__ Wr, const float* __restrict__ br,
                  float* __restrict__ out) {
    extern __shared__ unsigned smw[];                  // [2][201 rows x 100 u32]
    const uint4* W2b = (const uint4*)smw;              // row h at +h*25 uint4
    const uint4* W3b = (const uint4*)(smw + LSTRIDE);
    __shared__ float cnt_sm[L_GROUPS][HID];
    const int tid  = threadIdx.x;
    const int grp  = tid >> 5;
    const int lane = tid & 31;

    // fp32 -> bf16x2 pack; rows 0..199 = weights, row 200 = zeros
    for (int i = tid; i < HID * HID / 2; i += L_THREADS) {
        float2 a2 = *(const float2*)(W2 + 2 * i);
        float2 a3 = *(const float2*)(W3 + 2 * i);
        smw[i]           = bf16x2of(a2.x, a2.y);
        smw[LSTRIDE + i] = bf16x2of(a3.x, a3.y);
    }
    for (int i = tid; i < 100; i += L_THREADS) {
        smw[HID * HID / 2 + i]           = 0u;         // W2 zero row
        smw[LSTRIDE + HID * HID / 2 + i] = 0u;         // W3 zero row
    }

    const bool iv   = (lane < 25);
    const int  lidx = iv ? lane : 0;
    ull bias2[4] = {0,0,0,0}, bias3[4] = {0,0,0,0};
    if (iv) {
        #pragma unroll
        for (int q = 0; q < 4; q++) {
            float2 u2 = *(const float2*)(b2 + 8 * lane + 2 * q);
            float2 u3 = *(const float2*)(b3 + 8 * lane + 2 * q);
            bias2[q] = pack2(u2.x, u2.y);
            bias3[q] = pack2(u3.x, u3.y);
        }
    }
    __syncthreads();

    const int b = blockIdx.x * L_GROUPS + grp;
    if (b >= BATCH) return;                            // warp-uniform

    float v1[8], v2[8], v3[8];
    int cnt[8];
    unsigned mk2p[8];                                  // mk2 from previous t
    #pragma unroll
    for (int e = 0; e < 8; e++) {
        v1[e] = 0.f; v2[e] = 0.f; v3[e] = 0.f; cnt[e] = 0; mk2p[e] = 0u;
    }
    const float* curb = g_cur + (size_t)b * S_LEN * HID + (iv ? 8 * lane : 0);

    float4 bufA[4], bufB[4];
    #pragma unroll
    for (int q = 0; q < 4; q++) {
        bufA[q] = *(const float4*)(curb + q * HID);
        bufB[q] = *(const float4*)(curb + q * HID + 4);
    }

    for (int k = 0; k <= S_LEN; k++) {
        const bool prod = (k < S_LEN);
        unsigned mk1[8];
        if (prod) {
            float a[8];
            { float4 ca = bufA[k & 3], cb = bufB[k & 3];
              a[0]=ca.x; a[1]=ca.y; a[2]=ca.z; a[3]=ca.w;
              a[4]=cb.x; a[5]=cb.y; a[6]=cb.z; a[7]=cb.w; }
            int tp = k + 4; if (tp > S_LEN - 1) tp = S_LEN - 1;
            bufA[k & 3] = *(const float4*)(curb + (size_t)tp * HID);
            bufB[k & 3] = *(const float4*)(curb + (size_t)tp * HID + 4);

            #pragma unroll
            for (int e = 0; e < 8; e++) {
                v1[e] = 0.5f * (v1[e] + a[e]);
                bool s = iv && (v1[e] >= 1.0f);
                if (s) v1[e] = 0.f;
                mk1[e] = __ballot_sync(0xffffffffu, s);
            }
        } else {
            #pragma unroll
            for (int e = 0; e < 8; e++) mk1[e] = 0u;
        }

        // ---- dual interleaved scan: layer 2 (mk1, t=k) + layer 3 (mk2p, t=k-1)
        ull acc2[4] = { bias2[0], bias2[1], bias2[2], bias2[3] };
        ull acc3[4] = { bias3[0], bias3[1], bias3[2], bias3[3] };
        #pragma unroll
        for (int m = 0; m < 8; m++) {
            unsigned u2 = mk1[m], u3 = mk2p[m];
            while (u2 | u3) {                          // uniform across warp
                int j2 = __ffs(u2);
                int j3 = __ffs(u3);
                int h2 = j2 ? 8 * (j2 - 1) + m : 200;  // 200 = zero row
                int h3 = j3 ? 8 * (j3 - 1) + m : 200;
                u2 = j2 ? (u2 & (u2 - 1)) : 0u;
                u3 = j3 ? (u3 & (u3 - 1)) : 0u;
                const uint4 w2 = W2b[h2 * 25 + lidx];  // independent chains
                const uint4 w3 = W3b[h3 * 25 + lidx];
                acc2[0] = add2(acc2[0], pack2(bfLO(w2.x), bfHI(w2.x)));
                acc3[0] = add2(acc3[0], pack2(bfLO(w3.x), bfHI(w3.x)));
                acc2[1] = add2(acc2[1], pack2(bfLO(w2.y), bfHI(w2.y)));
                acc3[1] = add2(acc3[1], pack2(bfLO(w3.y), bfHI(w3.y)));
                acc2[2] = add2(acc2[2], pack2(bfLO(w2.z), bfHI(w2.z)));
                acc3[2] = add2(acc3[2], pack2(bfLO(w3.z), bfHI(w3.z)));
                acc2[3] = add2(acc2[3], pack2(bfLO(w2.w), bfHI(w2.w)));
                acc3[3] = add2(acc3[3], pack2(bfLO(w3.w), bfHI(w3.w)));
            }
        }

        if (prod) {                                    // LIF2 for t=k
            float c[8];
            unpack2(acc2[0], c[0], c[1]); unpack2(acc2[1], c[2], c[3]);
            unpack2(acc2[2], c[4], c[5]); unpack2(acc2[3], c[6], c[7]);
            #pragma unroll
            for (int e = 0; e < 8; e++) {
                v2[e] = 0.5f * (v2[e] + c[e]);
                bool s = iv && (v2[e] >= 1.0f);
                if (s) v2[e] = 0.f;
                mk2p[e] = __ballot_sync(0xffffffffu, s);
            }
        }
        if (k >= 1) {                                  // LIF3 for t=k-1
            float d[8];
            unpack2(acc3[0], d[0], d[1]); unpack2(acc3[1], d[2], d[3]);
            unpack2(acc3[2], d[4], d[5]); unpack2(acc3[3], d[6], d[7]);
            #pragma unroll
            for (int e = 0; e < 8; e++) {
                v3[e] = 0.5f * (v3[e] + d[e]);
                if (v3[e] >= 1.0f) { v3[e] = 0.f; cnt[e]++; }
            }
        }
    }

    if (iv) {
        *(float4*)&cnt_sm[grp][8 * lane] =
            make_float4((float)cnt[0], (float)cnt[1], (float)cnt[2], (float)cnt[3]);
        *(float4*)&cnt_sm[grp][8 * lane + 4] =
            make_float4((float)cnt[4], (float)cnt[5], (float)cnt[6], (float)cnt[7]);
    }
    __syncwarp();

    // fused readout + log_softmax
    float o = -3.0e38f;
    if (lane < DOUT) {
        float acc = 0.f;
        #pragma unroll 4
        for (int k = 0; k < HID; k++)
            acc += cnt_sm[grp][k] * Wr[k * DOUT + lane];
        o = acc * (1.0f / 101.0f) + br[lane];
    }
    float mx = o;
    #pragma unroll
    for (int off = 16; off; off >>= 1)
        mx = fmaxf(mx, __shfl_xor_sync(0xffffffffu, mx, off));
    float e = (lane < DOUT) ? expf(o - mx) : 0.f;
    float ssum = e;
    #pragma unroll
    for (int off = 16; off; off >>= 1)
        ssum += __shfl_xor_sync(0xffffffffu, ssum, off);
    if (lane < DOUT) out[b * DOUT + lane] = (o - mx) - logf(ssum);
}

// ================= launch ====================================================
extern "C" void kernel_launch(void* const* d_in, const int* in_sizes, int n_in,
                              void* d_out, int out_size) {
    const float* x  = (const float*)d_in[0];
    const float* W1 = (const float*)d_in[1];
    const float* b1 = (const float*)d_in[2];
    const float* W2 = (const float*)d_in[3];
    const float* b2 = (const float*)d_in[4];
    const float* W3 = (const float*)d_in[5];
    const float* b3 = (const float*)d_in[6];
    const float* Wr = (const float*)d_in[7];
    const float* br = (const float*)d_in[8];
    float* out = (float*)d_out;

    cudaFuncSetAttribute(gemm1_mma_kernel, cudaFuncAttributeMaxDynamicSharedMemorySize, BF_BYTES);
    cudaFuncSetAttribute(lif23_kernel,     cudaFuncAttributeMaxDynamicSharedMemorySize, LF_SMEM);

    const int grid = 148;

    gemm1_mma_kernel<<<grid, GM_THREADS, BF_BYTES>>>(x, W1, b1);
    lif23_kernel   <<<grid, L_THREADS,   LF_SMEM>>>(W2, b2, W3, b3, Wr, br, out);
}